// round 2
// baseline (speedup 1.0000x reference)
#include <cuda_runtime.h>
#include <math.h>

// Problem constants
#define TTOK   512
#define NH     64
#define DM     576
#define DVDIM  512
#define TOPKN  512

// Tiling
#define HPB    16                 // heads per block
#define KB     32                 // keys per tile
#define NTILES (TOPKN / KB)       // 16
#define KVR4   147                // padded kv smem row, float4 units (588 floats; 147 mod 8 = 3 -> conflict-free)
#define QR4    144                // 576/4
#define SROW   36                 // padded score row (floats)
#define NTHR   512
#define ATTN_SCALE 0.041666666666666664f   // 576^-0.5 = 1/24

// Shared memory layout (float offsets)
#define OFF_Q  0
#define OFF_KV (HPB * DM)                    // 9216
#define OFF_S  (OFF_KV + KB * (KVR4 * 4))    // 9216 + 18816 = 28032
#define OFF_A  (OFF_S + HPB * SROW)          // 28608
#define OFF_L  (OFF_A + HPB)                 // 28624
#define OFF_I  (OFF_L + HPB)                 // 28640
#define SMEM_FLOATS (OFF_I + KB)             // 28672
#define SMEM_BYTES  (SMEM_FLOATS * 4)        // 114688 B

__global__ __launch_bounds__(NTHR, 1)
void mla_fp32_kernel(const float* __restrict__ qg,
                     const float* __restrict__ kvg,
                     const int*   __restrict__ topk,
                     const float* __restrict__ sink,
                     float*       __restrict__ outg)
{
    extern __shared__ float sm[];
    float* q_s  = sm + OFF_Q;
    float* kv_s = sm + OFF_KV;
    float* s_s  = sm + OFF_S;
    float* a_s  = sm + OFF_A;
    float* l_s  = sm + OFF_L;
    int*   i_s  = (int*)(sm + OFF_I);

    const int g    = blockIdx.x;       // head group (0..3)
    const int t    = blockIdx.y;       // token
    const int tid  = threadIdx.x;
    const int lane = tid & 31;
    const int w    = tid >> 5;         // warp 0..15
    const int wq   = w & 3;            // head quad within block
    const int ko   = w >> 2;           // key octet within tile
    const int kl   = lane & 7;         // key within octet
    const int r    = lane >> 3;        // d-range split 0..3

    // ---- load Q tile (16 heads x 576) ----
    {
        const float4* src = (const float4*)qg + (size_t)(t * NH + g * HPB) * QR4;
        float4* dst = (float4*)q_s;
        for (int i = tid; i < HPB * QR4; i += NTHR) dst[i] = src[i];
    }

    // streaming softmax state, valid in warp w <-> head w
    float m_run = sink[g * HPB + w];
    float l_run = 1.0f;

    // O partial accumulators: 4 heads x 512 dims over 32 lanes, as 4x4 float4
    float4 oacc[4][4];
    #pragma unroll
    for (int a = 0; a < 4; ++a)
        #pragma unroll
        for (int b = 0; b < 4; ++b)
            oacc[a][b] = make_float4(0.f, 0.f, 0.f, 0.f);

    const int row_l = tid >> 4;        // gather: 32 rows x 16 threads
    const int fi    = tid & 15;
    const float4* kv4g = (const float4*)kvg;
    float4* kvs4 = (float4*)kv_s;

    for (int tile = 0; tile < NTILES; ++tile) {
        // ---------- gather-load K/V tile ----------
        int raw = topk[(size_t)t * TOPKN + tile * KB + row_l];
        if (tid < KB) i_s[tid] = topk[(size_t)t * TOPKN + tile * KB + tid];
        int rc = raw < 0 ? 0 : raw;
        const float4* srow = kv4g + (size_t)rc * QR4;
        #pragma unroll
        for (int j = 0; j < 9; ++j)
            kvs4[row_l * KVR4 + fi + 16 * j] = srow[fi + 16 * j];
        __syncthreads();

        // ---------- GEMM1: scores (4 heads x 8 keys per warp, d split 4 ways) ----------
        float s0 = 0.f, s1 = 0.f, s2 = 0.f, s3 = 0.f;
        const float4* kr = kvs4 + (ko * 8 + kl) * KVR4;
        const float4* qb = (const float4*)q_s + (wq * 4) * QR4;
        #pragma unroll 4
        for (int i = 0; i < 36; ++i) {
            int d4 = 4 * i + r;
            float4 kvv = kr[d4];
            float4 a0 = qb[d4];
            float4 a1 = qb[QR4 + d4];
            float4 a2 = qb[2 * QR4 + d4];
            float4 a3 = qb[3 * QR4 + d4];
            s0 = fmaf(a0.x, kvv.x, fmaf(a0.y, kvv.y, fmaf(a0.z, kvv.z, fmaf(a0.w, kvv.w, s0))));
            s1 = fmaf(a1.x, kvv.x, fmaf(a1.y, kvv.y, fmaf(a1.z, kvv.z, fmaf(a1.w, kvv.w, s1))));
            s2 = fmaf(a2.x, kvv.x, fmaf(a2.y, kvv.y, fmaf(a2.z, kvv.z, fmaf(a2.w, kvv.w, s2))));
            s3 = fmaf(a3.x, kvv.x, fmaf(a3.y, kvv.y, fmaf(a3.z, kvv.z, fmaf(a3.w, kvv.w, s3))));
        }
        // reduce the 4 d-splits (lanes differing in bits 3,4)
        s0 += __shfl_xor_sync(0xffffffffu, s0, 8);
        s0 += __shfl_xor_sync(0xffffffffu, s0, 16);
        s1 += __shfl_xor_sync(0xffffffffu, s1, 8);
        s1 += __shfl_xor_sync(0xffffffffu, s1, 16);
        s2 += __shfl_xor_sync(0xffffffffu, s2, 8);
        s2 += __shfl_xor_sync(0xffffffffu, s2, 16);
        s3 += __shfl_xor_sync(0xffffffffu, s3, 8);
        s3 += __shfl_xor_sync(0xffffffffu, s3, 16);

        int key = ko * 8 + kl;
        bool valid = (i_s[key] >= 0);
        s0 = valid ? s0 * ATTN_SCALE : -INFINITY;
        s1 = valid ? s1 * ATTN_SCALE : -INFINITY;
        s2 = valid ? s2 * ATTN_SCALE : -INFINITY;
        s3 = valid ? s3 * ATTN_SCALE : -INFINITY;
        if (r == 0) {
            s_s[(wq * 4 + 0) * SROW + key] = s0;
            s_s[(wq * 4 + 1) * SROW + key] = s1;
            s_s[(wq * 4 + 2) * SROW + key] = s2;
            s_s[(wq * 4 + 3) * SROW + key] = s3;
        }
        __syncthreads();

        // ---------- streaming softmax: warp w handles head w ----------
        {
            float sv = s_s[w * SROW + lane];
            float mt = sv;
            #pragma unroll
            for (int d = 16; d >= 1; d >>= 1)
                mt = fmaxf(mt, __shfl_xor_sync(0xffffffffu, mt, d));
            float m_new = fmaxf(m_run, mt);
            float al = __expf(m_run - m_new);
            float p  = __expf(sv - m_new);
            float ps = p;
            #pragma unroll
            for (int d = 16; d >= 1; d >>= 1)
                ps += __shfl_xor_sync(0xffffffffu, ps, d);
            l_run = l_run * al + ps;
            m_run = m_new;
            s_s[w * SROW + lane] = p;          // store probabilities in place
            if (lane == 0) a_s[w] = al;
        }
        __syncthreads();

        // ---------- GEMM2: O += P * V (same warp mapping: 4 heads x 8 keys) ----------
        {
            float al0 = a_s[wq * 4 + 0];
            float al1 = a_s[wq * 4 + 1];
            float al2 = a_s[wq * 4 + 2];
            float al3 = a_s[wq * 4 + 3];
            #pragma unroll
            for (int c = 0; c < 4; ++c) {
                oacc[0][c].x *= al0; oacc[0][c].y *= al0; oacc[0][c].z *= al0; oacc[0][c].w *= al0;
                oacc[1][c].x *= al1; oacc[1][c].y *= al1; oacc[1][c].z *= al1; oacc[1][c].w *= al1;
                oacc[2][c].x *= al2; oacc[2][c].y *= al2; oacc[2][c].z *= al2; oacc[2][c].w *= al2;
                oacc[3][c].x *= al3; oacc[3][c].y *= al3; oacc[3][c].z *= al3; oacc[3][c].w *= al3;
            }
            #pragma unroll 2
            for (int k = 0; k < 8; ++k) {
                int k2 = ko * 8 + k;
                float p0 = s_s[(wq * 4 + 0) * SROW + k2];
                float p1 = s_s[(wq * 4 + 1) * SROW + k2];
                float p2 = s_s[(wq * 4 + 2) * SROW + k2];
                float p3 = s_s[(wq * 4 + 3) * SROW + k2];
                const float4* vr = kvs4 + k2 * KVR4;
                #pragma unroll
                for (int c = 0; c < 4; ++c) {
                    float4 v = vr[c * 32 + lane];     // d' = c*128 + lane*4 (+0..3), all < 512
                    oacc[0][c].x = fmaf(p0, v.x, oacc[0][c].x);
                    oacc[0][c].y = fmaf(p0, v.y, oacc[0][c].y);
                    oacc[0][c].z = fmaf(p0, v.z, oacc[0][c].z);
                    oacc[0][c].w = fmaf(p0, v.w, oacc[0][c].w);
                    oacc[1][c].x = fmaf(p1, v.x, oacc[1][c].x);
                    oacc[1][c].y = fmaf(p1, v.y, oacc[1][c].y);
                    oacc[1][c].z = fmaf(p1, v.z, oacc[1][c].z);
                    oacc[1][c].w = fmaf(p1, v.w, oacc[1][c].w);
                    oacc[2][c].x = fmaf(p2, v.x, oacc[2][c].x);
                    oacc[2][c].y = fmaf(p2, v.y, oacc[2][c].y);
                    oacc[2][c].z = fmaf(p2, v.z, oacc[2][c].z);
                    oacc[2][c].w = fmaf(p2, v.w, oacc[2][c].w);
                    oacc[3][c].x = fmaf(p3, v.x, oacc[3][c].x);
                    oacc[3][c].y = fmaf(p3, v.y, oacc[3][c].y);
                    oacc[3][c].z = fmaf(p3, v.z, oacc[3][c].z);
                    oacc[3][c].w = fmaf(p3, v.w, oacc[3][c].w);
                }
            }
        }
        __syncthreads();   // protect kv_s / s_s before next tile
    }

    if (lane == 0) l_s[w] = l_run;
    __syncthreads();

    // ---- reduce the 4 key-octet partials into ostage (reuse Q smem) ----
    float4* ost = (float4*)q_s;
    #pragma unroll
    for (int pass = 0; pass < 4; ++pass) {
        if (ko == pass) {
            #pragma unroll
            for (int hh = 0; hh < 4; ++hh)
                #pragma unroll
                for (int c = 0; c < 4; ++c) {
                    int oi = (wq * 4 + hh) * 128 + c * 32 + lane;
                    if (pass == 0) {
                        ost[oi] = oacc[hh][c];
                    } else {
                        float4 cur = ost[oi];
                        cur.x += oacc[hh][c].x; cur.y += oacc[hh][c].y;
                        cur.z += oacc[hh][c].z; cur.w += oacc[hh][c].w;
                        ost[oi] = cur;
                    }
                }
        }
        __syncthreads();
    }

    // ---- normalize + write out: warp w <-> head w ----
    {
        float rl = 1.0f / l_s[w];
        float4* og = (float4*)outg + (size_t)(t * NH + g * HPB + w) * (DVDIM / 4);
        #pragma unroll
        for (int c = 0; c < 4; ++c) {
            float4 v = ost[w * 128 + c * 32 + lane];
            v.x *= rl; v.y *= rl; v.z *= rl; v.w *= rl;
            og[c * 32 + lane] = v;
        }
    }
}

extern "C" void kernel_launch(void* const* d_in, const int* in_sizes, int n_in,
                              void* d_out, int out_size)
{
    const float* q    = (const float*)d_in[0];
    const float* kv   = (const float*)d_in[1];
    const int*   topk = (const int*)d_in[2];
    const float* sink = (const float*)d_in[3];
    float* out = (float*)d_out;

    cudaFuncSetAttribute(mla_fp32_kernel,
                         cudaFuncAttributeMaxDynamicSharedMemorySize, SMEM_BYTES);
    dim3 grid(NH / HPB, TTOK);
    mla_fp32_kernel<<<grid, NTHR, SMEM_BYTES>>>(q, kv, topk, sink, out);
}

// round 7
// speedup vs baseline: 2.7308x; 2.7308x over previous
#include <cuda_runtime.h>
#include <cuda_bf16.h>
#include <math.h>
#include <stdint.h>

#define TTOK   512
#define NHD    64
#define DMODEL 576
#define DV     512
#define TOPKN  512
#define NKV    32768
#define NTHR   512
#define SCALE_F 0.041666666666666664f   // 576^-0.5

// ---------------- device scratch (bf16 hi/lo splits) ----------------
__device__ __nv_bfloat16 g_khi[(size_t)NKV * DMODEL];
__device__ __nv_bfloat16 g_klo[(size_t)NKV * DMODEL];
__device__ __nv_bfloat16 g_qhi[(size_t)TTOK * NHD * DMODEL];
__device__ __nv_bfloat16 g_qlo[(size_t)TTOK * NHD * DMODEL];

// ---------------- smem layout (bytes) ----------------
#define SM_IDX   0            // 512 ints
#define SM_REDM  2048         // 64x4 floats (row max per group)
#define SM_REDS  3072         // 64x4 floats (row sum per group)
#define SM_LH    4096         // 64 floats (1/l per head)
#define SM_MAIN  4608
// phase 1: Q chunk [64h x 64d] hi/lo (stride 72 bf16 = 144B), K chunk [512k x 64d] hi/lo
#define QC_HI    SM_MAIN                    // 9216
#define QC_LO    (SM_MAIN + 9216)           // 9216
#define KC_HI    (SM_MAIN + 18432)          // 73728
#define KC_LO    (SM_MAIN + 92160)          // 73728  (end 170496)
// phase 2: P [64h x 512k] hi/lo (stride 520 bf16 = 1040B), V chunk [32k x 512dv] hi/lo
#define P_HI     SM_MAIN                    // 66560
#define P_LO     (SM_MAIN + 66560)          // 66560
#define VC_HI    (SM_MAIN + 133120)         // 33280
#define VC_LO    (SM_MAIN + 166400)         // 33280  (end 199680)
#define SMEM_TOTAL 204288

// ---------------- helpers ----------------
__device__ __forceinline__ uint32_t smem_u32(const void* p) {
    uint32_t a;
    asm("{ .reg .u64 t; cvta.to.shared.u64 t, %1; cvt.u32.u64 %0, t; }" : "=r"(a) : "l"(p));
    return a;
}

__device__ __forceinline__ void ldsm_x4(uint32_t* r, uint32_t addr) {
    asm volatile("ldmatrix.sync.aligned.m8n8.x4.shared.b16 {%0,%1,%2,%3}, [%4];"
                 : "=r"(r[0]), "=r"(r[1]), "=r"(r[2]), "=r"(r[3]) : "r"(addr));
}
__device__ __forceinline__ void ldsm_x4t(uint32_t* r, uint32_t addr) {
    asm volatile("ldmatrix.sync.aligned.m8n8.x4.trans.shared.b16 {%0,%1,%2,%3}, [%4];"
                 : "=r"(r[0]), "=r"(r[1]), "=r"(r[2]), "=r"(r[3]) : "r"(addr));
}
__device__ __forceinline__ void mma_bf16(float* c, const uint32_t* a, uint32_t b0, uint32_t b1) {
    asm volatile("mma.sync.aligned.m16n8k16.row.col.f32.bf16.bf16.f32 "
                 "{%0,%1,%2,%3}, {%4,%5,%6,%7}, {%8,%9}, {%0,%1,%2,%3};"
                 : "+f"(c[0]), "+f"(c[1]), "+f"(c[2]), "+f"(c[3])
                 : "r"(a[0]), "r"(a[1]), "r"(a[2]), "r"(a[3]), "r"(b0), "r"(b1));
}

// ---------------- conversion pre-kernels ----------------
__global__ void conv_kv_kernel(const float4* __restrict__ src) {
    int i = blockIdx.x * blockDim.x + threadIdx.x;
    float4 v = src[i];
    __nv_bfloat16 h0 = __float2bfloat16_rn(v.x), h1 = __float2bfloat16_rn(v.y);
    __nv_bfloat16 h2 = __float2bfloat16_rn(v.z), h3 = __float2bfloat16_rn(v.w);
    __nv_bfloat162* hi = (__nv_bfloat162*)g_khi;
    __nv_bfloat162* lo = (__nv_bfloat162*)g_klo;
    hi[2*i]   = __nv_bfloat162(h0, h1);
    hi[2*i+1] = __nv_bfloat162(h2, h3);
    lo[2*i]   = __nv_bfloat162(__float2bfloat16_rn(v.x - __bfloat162float(h0)),
                               __float2bfloat16_rn(v.y - __bfloat162float(h1)));
    lo[2*i+1] = __nv_bfloat162(__float2bfloat16_rn(v.z - __bfloat162float(h2)),
                               __float2bfloat16_rn(v.w - __bfloat162float(h3)));
}
__global__ void conv_q_kernel(const float4* __restrict__ src) {
    int i = blockIdx.x * blockDim.x + threadIdx.x;
    float4 v = src[i];
    __nv_bfloat16 h0 = __float2bfloat16_rn(v.x), h1 = __float2bfloat16_rn(v.y);
    __nv_bfloat16 h2 = __float2bfloat16_rn(v.z), h3 = __float2bfloat16_rn(v.w);
    __nv_bfloat162* hi = (__nv_bfloat162*)g_qhi;
    __nv_bfloat162* lo = (__nv_bfloat162*)g_qlo;
    hi[2*i]   = __nv_bfloat162(h0, h1);
    hi[2*i+1] = __nv_bfloat162(h2, h3);
    lo[2*i]   = __nv_bfloat162(__float2bfloat16_rn(v.x - __bfloat162float(h0)),
                               __float2bfloat16_rn(v.y - __bfloat162float(h1)));
    lo[2*i+1] = __nv_bfloat162(__float2bfloat16_rn(v.z - __bfloat162float(h2)),
                               __float2bfloat16_rn(v.w - __bfloat162float(h3)));
}

// ---------------- main attention kernel ----------------
__global__ __launch_bounds__(NTHR, 1)
void mla_mma_kernel(const int* __restrict__ topk,
                    const float* __restrict__ sink,
                    float* __restrict__ outg)
{
    extern __shared__ char smem[];
    const uint32_t sbase = smem_u32(smem);
    const int tid  = threadIdx.x;
    const int lane = tid & 31;
    const int w    = tid >> 5;
    const int hb   = w & 3;          // head block (16 heads)
    const int g    = w >> 2;         // 128-key / 128-dv slice
    const int t    = blockIdx.x;

    int*   idx_s = (int*)(smem + SM_IDX);
    float* redm  = (float*)(smem + SM_REDM);
    float* reds  = (float*)(smem + SM_REDS);
    float* lh    = (float*)(smem + SM_LH);

    idx_s[tid] = topk[(size_t)t * TOPKN + tid];
    __syncthreads();

    float acc[16][4];
    #pragma unroll
    for (int i = 0; i < 16; ++i)
        #pragma unroll
        for (int j = 0; j < 4; ++j) acc[i][j] = 0.f;

    const int lo16 = lane & 15, hi16 = lane >> 4;
    const uint32_t aQh = sbase + QC_HI + (16 * hb + lo16) * 144 + hi16 * 16;
    const uint32_t aQl = aQh + 9216;
    const uint32_t bKh = sbase + KC_HI + (128 * g + lo16) * 144 + hi16 * 16;
    const uint32_t bKl = bKh + 73728;

    // ================= GEMM1: S = Q K^T, 9 d-chunks of 64 =================
    #pragma unroll 1
    for (int dc = 0; dc < 9; ++dc) {
        {   // Q chunk: 64 rows x 64 d, 8 threads/row
            int row = tid >> 3, q = tid & 7;
            size_t so = (size_t)(t * NHD + row) * DMODEL + dc * 64 + q * 8;
            uint32_t doff = QC_HI + row * 144 + q * 16;
            *(uint4*)(smem + doff)        = *(const uint4*)(g_qhi + so);
            *(uint4*)(smem + doff + 9216) = *(const uint4*)(g_qlo + so);
        }
        {   // K chunk gather: 512 rows x 64 d
            int rb = tid >> 3, q = tid & 7;
            #pragma unroll
            for (int pass = 0; pass < 8; ++pass) {
                int krow = pass * 64 + rb;
                int id = idx_s[krow]; id = id < 0 ? 0 : id;
                size_t so = (size_t)id * DMODEL + dc * 64 + q * 8;
                uint32_t doff = KC_HI + krow * 144 + q * 16;
                *(uint4*)(smem + doff)         = *(const uint4*)(g_khi + so);
                *(uint4*)(smem + doff + 73728) = *(const uint4*)(g_klo + so);
            }
        }
        __syncthreads();
        #pragma unroll
        for (int kk = 0; kk < 4; ++kk) {
            uint32_t aH[4], aL[4];
            ldsm_x4(aH, aQh + kk * 32);
            ldsm_x4(aL, aQl + kk * 32);
            #pragma unroll
            for (int np = 0; np < 8; ++np) {
                uint32_t bH[4], bL[4];
                ldsm_x4(bH, bKh + np * 2304 + kk * 32);
                ldsm_x4(bL, bKl + np * 2304 + kk * 32);
                mma_bf16(acc[2*np],   aH, bH[0], bH[2]);
                mma_bf16(acc[2*np],   aH, bL[0], bL[2]);
                mma_bf16(acc[2*np],   aL, bH[0], bH[2]);
                mma_bf16(acc[2*np+1], aH, bH[1], bH[3]);
                mma_bf16(acc[2*np+1], aH, bL[1], bL[3]);
                mma_bf16(acc[2*np+1], aL, bH[1], bH[3]);
            }
        }
        __syncthreads();
    }

    // ================= softmax on register fragments =================
    const int r0 = lane >> 2;
    const int h0 = 16 * hb + r0, h1 = h0 + 8;
    const int c0 = 2 * (lane & 3);
    float m0 = -1e30f, m1 = -1e30f;
    uint32_t vm = 0;
    #pragma unroll
    for (int nt = 0; nt < 16; ++nt) {
        int key = 128 * g + 8 * nt + c0;
        bool v0 = idx_s[key] >= 0, v1 = idx_s[key + 1] >= 0;
        acc[nt][0] *= SCALE_F; acc[nt][1] *= SCALE_F;
        acc[nt][2] *= SCALE_F; acc[nt][3] *= SCALE_F;
        if (v0) { m0 = fmaxf(m0, acc[nt][0]); m1 = fmaxf(m1, acc[nt][2]); vm |= 1u << (2*nt); }
        if (v1) { m0 = fmaxf(m0, acc[nt][1]); m1 = fmaxf(m1, acc[nt][3]); vm |= 2u << (2*nt); }
    }
    m0 = fmaxf(m0, __shfl_xor_sync(0xffffffffu, m0, 1));
    m0 = fmaxf(m0, __shfl_xor_sync(0xffffffffu, m0, 2));
    m1 = fmaxf(m1, __shfl_xor_sync(0xffffffffu, m1, 1));
    m1 = fmaxf(m1, __shfl_xor_sync(0xffffffffu, m1, 2));
    if ((lane & 3) == 0) { redm[h0 * 4 + g] = m0; redm[h1 * 4 + g] = m1; }
    __syncthreads();
    float sk0 = sink[h0], sk1 = sink[h1];
    float mf0 = fmaxf(fmaxf(fmaxf(redm[h0*4+0], redm[h0*4+1]), fmaxf(redm[h0*4+2], redm[h0*4+3])), sk0);
    float mf1 = fmaxf(fmaxf(fmaxf(redm[h1*4+0], redm[h1*4+1]), fmaxf(redm[h1*4+2], redm[h1*4+3])), sk1);
    float l0 = 0.f, l1 = 0.f;
    #pragma unroll
    for (int nt = 0; nt < 16; ++nt) {
        int key = 128 * g + 8 * nt + c0;
        float p00 = ((vm >> (2*nt)) & 1) ? __expf(acc[nt][0] - mf0) : 0.f;
        float p01 = ((vm >> (2*nt)) & 2) ? __expf(acc[nt][1] - mf0) : 0.f;
        float p10 = ((vm >> (2*nt)) & 1) ? __expf(acc[nt][2] - mf1) : 0.f;
        float p11 = ((vm >> (2*nt)) & 2) ? __expf(acc[nt][3] - mf1) : 0.f;
        l0 += p00 + p01; l1 += p10 + p11;
        __nv_bfloat16 a0 = __float2bfloat16_rn(p00), a1 = __float2bfloat16_rn(p01);
        __nv_bfloat16 b0 = __float2bfloat16_rn(p10), b1 = __float2bfloat16_rn(p11);
        __nv_bfloat162 h_r0(a0, a1), h_r1(b0, b1);
        __nv_bfloat162 l_r0(__float2bfloat16_rn(p00 - __bfloat162float(a0)),
                            __float2bfloat16_rn(p01 - __bfloat162float(a1)));
        __nv_bfloat162 l_r1(__float2bfloat16_rn(p10 - __bfloat162float(b0)),
                            __float2bfloat16_rn(p11 - __bfloat162float(b1)));
        *(__nv_bfloat162*)(smem + P_HI + h0 * 1040 + key * 2) = h_r0;
        *(__nv_bfloat162*)(smem + P_HI + h1 * 1040 + key * 2) = h_r1;
        *(__nv_bfloat162*)(smem + P_LO + h0 * 1040 + key * 2) = l_r0;
        *(__nv_bfloat162*)(smem + P_LO + h1 * 1040 + key * 2) = l_r1;
    }
    l0 += __shfl_xor_sync(0xffffffffu, l0, 1);
    l0 += __shfl_xor_sync(0xffffffffu, l0, 2);
    l1 += __shfl_xor_sync(0xffffffffu, l1, 1);
    l1 += __shfl_xor_sync(0xffffffffu, l1, 2);
    if ((lane & 3) == 0) { reds[h0 * 4 + g] = l0; reds[h1 * 4 + g] = l1; }
    __syncthreads();
    if (g == 0 && (lane & 3) == 0) {
        float la = reds[h0*4+0] + reds[h0*4+1] + reds[h0*4+2] + reds[h0*4+3] + __expf(sk0 - mf0);
        float lb = reds[h1*4+0] + reds[h1*4+1] + reds[h1*4+2] + reds[h1*4+3] + __expf(sk1 - mf1);
        lh[h0] = 1.0f / la;
        lh[h1] = 1.0f / lb;
    }

    // zero accumulators for GEMM2
    #pragma unroll
    for (int i = 0; i < 16; ++i)
        #pragma unroll
        for (int j = 0; j < 4; ++j) acc[i][j] = 0.f;

    // ================= GEMM2: O = P V, 16 key tiles of 32 =================
    const uint32_t aPh = sbase + P_HI + (16 * hb + lo16) * 1040 + hi16 * 16;
    const uint32_t aPl = aPh + 66560;
    const uint32_t bVh = sbase + VC_HI + lo16 * 1040 + hi16 * 16 + 256 * g;
    const uint32_t bVl = bVh + 33280;
    #pragma unroll 1
    for (int vt = 0; vt < 16; ++vt) {
        {   // V tile gather: 32 rows x 512 dv, 16 threads/row
            int row = tid >> 4, q0 = tid & 15;
            int id = idx_s[vt * 32 + row]; id = id < 0 ? 0 : id;
            const __nv_bfloat16* sh = g_khi + (size_t)id * DMODEL;
            const __nv_bfloat16* sl = g_klo + (size_t)id * DMODEL;
            #pragma unroll
            for (int j = 0; j < 4; ++j) {
                int q = q0 + 16 * j;
                uint32_t doff = VC_HI + row * 1040 + q * 16;
                *(uint4*)(smem + doff)         = *(const uint4*)(sh + q * 8);
                *(uint4*)(smem + doff + 33280) = *(const uint4*)(sl + q * 8);
            }
        }
        __syncthreads();
        #pragma unroll
        for (int kk2 = 0; kk2 < 2; ++kk2) {
            uint32_t aH[4], aL[4];
            ldsm_x4(aH, aPh + vt * 64 + kk2 * 32);
            ldsm_x4(aL, aPl + vt * 64 + kk2 * 32);
            #pragma unroll
            for (int np = 0; np < 8; ++np) {
                uint32_t bH[4], bL[4];
                ldsm_x4t(bH, bVh + kk2 * 16640 + np * 32);
                ldsm_x4t(bL, bVl + kk2 * 16640 + np * 32);
                mma_bf16(acc[2*np],   aH, bH[0], bH[1]);
                mma_bf16(acc[2*np],   aH, bL[0], bL[1]);
                mma_bf16(acc[2*np],   aL, bH[0], bH[1]);
                mma_bf16(acc[2*np+1], aH, bH[2], bH[3]);
                mma_bf16(acc[2*np+1], aH, bL[2], bL[3]);
                mma_bf16(acc[2*np+1], aL, bH[2], bH[3]);
            }
        }
        __syncthreads();
    }

    // ================= normalize + write =================
    float li0 = lh[h0], li1 = lh[h1];
    float* ob0 = outg + ((size_t)t * NHD + h0) * DV + 128 * g + c0;
    float* ob1 = outg + ((size_t)t * NHD + h1) * DV + 128 * g + c0;
    #pragma unroll
    for (int nt = 0; nt < 16; ++nt) {
        float2 v0 = make_float2(acc[nt][0] * li0, acc[nt][1] * li0);
        float2 v1 = make_float2(acc[nt][2] * li1, acc[nt][3] * li1);
        *(float2*)(ob0 + 8 * nt) = v0;
        *(float2*)(ob1 + 8 * nt) = v1;
    }
}

// ---------------- launcher ----------------
extern "C" void kernel_launch(void* const* d_in, const int* in_sizes, int n_in,
                              void* d_out, int out_size)
{
    const float* q    = (const float*)d_in[0];
    const float* kv   = (const float*)d_in[1];
    const int*   topk = (const int*)d_in[2];
    const float* sink = (const float*)d_in[3];
    float* out = (float*)d_out;

    const int n4 = 4718592;   // 18,874,368 floats / 4 (both q and kv)
    conv_kv_kernel<<<n4 / 256, 256>>>((const float4*)kv);
    conv_q_kernel<<<n4 / 256, 256>>>((const float4*)q);

    cudaFuncSetAttribute(mla_mma_kernel,
                         cudaFuncAttributeMaxDynamicSharedMemorySize, SMEM_TOTAL);
    mla_mma_kernel<<<TTOK, NTHR, SMEM_TOTAL>>>(topk, sink, out);
}

// round 10
// speedup vs baseline: 3.3880x; 1.2407x over previous
#include <cuda_runtime.h>
#include <cuda_bf16.h>
#include <math.h>
#include <stdint.h>

#define TTOK   512
#define NHD    64
#define DMODEL 576
#define DV     512
#define TOPKN  512
#define NKV    32768
#define NTHR   512
#define SCALE_F 0.041666666666666664f   // 576^-0.5

// ---------------- device scratch (bf16 hi/lo split of kv_cache) ----------------
__device__ __nv_bfloat16 g_khi[(size_t)NKV * DMODEL];
__device__ __nv_bfloat16 g_klo[(size_t)NKV * DMODEL];

// ---------------- smem layout (bytes) ----------------
#define SM_IDX   0            // 512 ints
#define SM_REDM  2048         // 64x4 floats
#define SM_REDS  3072         // 64x4 floats
#define SM_LH    4096         // 64 floats
// phase 1: Q buffers [64h x 32d] hi/lo (stride 40 bf16 = 80B), K buffers [512k x 32d] hi/lo
#define QB0      4608         // per buffer: hi 5120 + lo 5120 = 10240; x2 -> ends 25088
#define KB0      25088        // per buffer: hi 40960 + lo 40960 = 81920; x2 -> ends 188928
// phase 2 (union, after GEMM1): P [64h x 512k] hi/lo (stride 520 bf16 = 1040B)
#define P_HI     4608         // 66560
#define P_LO     71168        // 66560 -> ends 137728
#define VB0      137728       // per buffer: hi 16640 + lo 16640 = 33280; x2 -> ends 204288
#define SMEM_TOTAL 204288

// ---------------- helpers ----------------
__device__ __forceinline__ uint32_t smem_u32(const void* p) {
    uint32_t a;
    asm("{ .reg .u64 t; cvta.to.shared.u64 t, %1; cvt.u32.u64 %0, t; }" : "=r"(a) : "l"(p));
    return a;
}
__device__ __forceinline__ void ldsm_x4(uint32_t* r, uint32_t addr) {
    asm volatile("ldmatrix.sync.aligned.m8n8.x4.shared.b16 {%0,%1,%2,%3}, [%4];"
                 : "=r"(r[0]), "=r"(r[1]), "=r"(r[2]), "=r"(r[3]) : "r"(addr));
}
__device__ __forceinline__ void ldsm_x4t(uint32_t* r, uint32_t addr) {
    asm volatile("ldmatrix.sync.aligned.m8n8.x4.trans.shared.b16 {%0,%1,%2,%3}, [%4];"
                 : "=r"(r[0]), "=r"(r[1]), "=r"(r[2]), "=r"(r[3]) : "r"(addr));
}
__device__ __forceinline__ void mma_bf16(float* c, const uint32_t* a, uint32_t b0, uint32_t b1) {
    asm volatile("mma.sync.aligned.m16n8k16.row.col.f32.bf16.bf16.f32 "
                 "{%0,%1,%2,%3}, {%4,%5,%6,%7}, {%8,%9}, {%0,%1,%2,%3};"
                 : "+f"(c[0]), "+f"(c[1]), "+f"(c[2]), "+f"(c[3])
                 : "r"(a[0]), "r"(a[1]), "r"(a[2]), "r"(a[3]), "r"(b0), "r"(b1));
}
__device__ __forceinline__ void cp16(uint32_t dst, const void* src) {
    asm volatile("cp.async.cg.shared.global [%0], [%1], 16;" :: "r"(dst), "l"(src));
}
#define CP_COMMIT() asm volatile("cp.async.commit_group;" ::: "memory")
#define CP_WAIT1()  asm volatile("cp.async.wait_group 1;" ::: "memory")
#define CP_WAIT0()  asm volatile("cp.async.wait_group 0;" ::: "memory")

// ---------------- kv conversion pre-kernel ----------------
__global__ void conv_kv_kernel(const float4* __restrict__ src) {
    int i = blockIdx.x * blockDim.x + threadIdx.x;
    float4 v = src[i];
    __nv_bfloat16 h0 = __float2bfloat16_rn(v.x), h1 = __float2bfloat16_rn(v.y);
    __nv_bfloat16 h2 = __float2bfloat16_rn(v.z), h3 = __float2bfloat16_rn(v.w);
    __nv_bfloat162* hi = (__nv_bfloat162*)g_khi;
    __nv_bfloat162* lo = (__nv_bfloat162*)g_klo;
    hi[2*i]   = __nv_bfloat162(h0, h1);
    hi[2*i+1] = __nv_bfloat162(h2, h3);
    lo[2*i]   = __nv_bfloat162(__float2bfloat16_rn(v.x - __bfloat162float(h0)),
                               __float2bfloat16_rn(v.y - __bfloat162float(h1)));
    lo[2*i+1] = __nv_bfloat162(__float2bfloat16_rn(v.z - __bfloat162float(h2)),
                               __float2bfloat16_rn(v.w - __bfloat162float(h3)));
}

// ---------------- main attention kernel ----------------
__global__ __launch_bounds__(NTHR, 1)
void mla_mma_kernel(const float* __restrict__ qg,
                    const int* __restrict__ topk,
                    const float* __restrict__ sink,
                    float* __restrict__ outg)
{
    extern __shared__ char smem[];
    const uint32_t sbase = smem_u32(smem);
    const int tid  = threadIdx.x;
    const int lane = tid & 31;
    const int w    = tid >> 5;
    const int hb   = w & 3;          // head block (16 heads)
    const int g    = w >> 2;         // 128-key / 128-dv slice
    const int t    = blockIdx.x;

    int*   idx_s = (int*)(smem + SM_IDX);
    float* redm  = (float*)(smem + SM_REDM);
    float* reds  = (float*)(smem + SM_REDS);
    float* lh    = (float*)(smem + SM_LH);

    idx_s[tid] = topk[(size_t)t * TOPKN + tid];
    __syncthreads();

    float acc[16][4];
    #pragma unroll
    for (int i = 0; i < 16; ++i)
        #pragma unroll
        for (int j = 0; j < 4; ++j) acc[i][j] = 0.f;

    const int lo16 = lane & 15, hi16 = lane >> 4;

    // ---- loader lambdas ----
    auto loadQ = [&](int dc, int b) {
        int row = tid >> 3, q = tid & 7;
        float4 v = *(const float4*)(qg + (size_t)(t * NHD + row) * DMODEL + dc * 32 + q * 4);
        __nv_bfloat16 h0 = __float2bfloat16_rn(v.x), h1 = __float2bfloat16_rn(v.y);
        __nv_bfloat16 h2 = __float2bfloat16_rn(v.z), h3 = __float2bfloat16_rn(v.w);
        char* dst = smem + QB0 + b * 10240 + row * 80 + q * 8;
        *(__nv_bfloat162*)(dst)          = __nv_bfloat162(h0, h1);
        *(__nv_bfloat162*)(dst + 4)      = __nv_bfloat162(h2, h3);
        *(__nv_bfloat162*)(dst + 5120)   = __nv_bfloat162(__float2bfloat16_rn(v.x - __bfloat162float(h0)),
                                                          __float2bfloat16_rn(v.y - __bfloat162float(h1)));
        *(__nv_bfloat162*)(dst + 5124)   = __nv_bfloat162(__float2bfloat16_rn(v.z - __bfloat162float(h2)),
                                                          __float2bfloat16_rn(v.w - __bfloat162float(h3)));
    };
    auto issueK = [&](int dc, int b) {
        int rb = tid >> 3, q = tid & 7;
        int half = q >> 2, s = q & 3;
        uint32_t base = sbase + KB0 + b * 81920 + half * 40960;
        const __nv_bfloat16* gk = half ? g_klo : g_khi;
        #pragma unroll
        for (int pass = 0; pass < 8; ++pass) {
            int krow = pass * 64 + rb;
            int id = idx_s[krow]; id = id < 0 ? 0 : id;
            cp16(base + krow * 80 + s * 16, gk + (size_t)id * DMODEL + dc * 32 + s * 8);
        }
    };
    auto issueV = [&](int vt, int b) {
        int row = tid >> 5;
        int id = idx_s[vt * 16 + row]; id = id < 0 ? 0 : id;
        #pragma unroll
        for (int j = 0; j < 4; ++j) {
            int seg = lane + 32 * j;
            int half = seg >> 6, s = seg & 63;
            const __nv_bfloat16* gk = half ? g_klo : g_khi;
            cp16(sbase + VB0 + b * 33280 + half * 16640 + row * 1040 + s * 16,
                 gk + (size_t)id * DMODEL + s * 8);
        }
    };

    // ================= GEMM1: S = Q K^T, 18 d-chunks of 32, pipelined =================
    loadQ(0, 0); issueK(0, 0); CP_COMMIT();
    int buf = 0;
    #pragma unroll 1
    for (int dc = 0; dc < 18; ++dc) {
        int nb = buf ^ 1;
        if (dc + 1 < 18) { loadQ(dc + 1, nb); issueK(dc + 1, nb); CP_COMMIT(); CP_WAIT1(); }
        else             { CP_WAIT0(); }
        __syncthreads();
        {
            uint32_t qb = sbase + QB0 + buf * 10240 + (16 * hb + lo16) * 80 + hi16 * 16;
            uint32_t kb = sbase + KB0 + buf * 81920 + (128 * g + lo16) * 80 + hi16 * 16;
            #pragma unroll
            for (int kk = 0; kk < 2; ++kk) {
                uint32_t aH[4], aL[4];
                ldsm_x4(aH, qb + kk * 32);
                ldsm_x4(aL, qb + 5120 + kk * 32);
                #pragma unroll
                for (int np = 0; np < 8; ++np) {
                    uint32_t bH[4], bL[4];
                    ldsm_x4(bH, kb + np * 1280 + kk * 32);
                    ldsm_x4(bL, kb + 40960 + np * 1280 + kk * 32);
                    mma_bf16(acc[2*np],   aH, bH[0], bH[2]);
                    mma_bf16(acc[2*np],   aH, bL[0], bL[2]);
                    mma_bf16(acc[2*np],   aL, bH[0], bH[2]);
                    mma_bf16(acc[2*np+1], aH, bH[1], bH[3]);
                    mma_bf16(acc[2*np+1], aH, bL[1], bL[3]);
                    mma_bf16(acc[2*np+1], aL, bH[1], bH[3]);
                }
            }
        }
        __syncthreads();
        buf = nb;
    }

    // issue V tile 0 load now (K/Q buffers dead; overlaps softmax)
    issueV(0, 0); CP_COMMIT();

    // ================= softmax on register fragments =================
    const int r0 = lane >> 2;
    const int h0 = 16 * hb + r0, h1 = h0 + 8;
    const int c0 = 2 * (lane & 3);
    float m0 = -1e30f, m1 = -1e30f;
    uint32_t vm = 0;
    #pragma unroll
    for (int nt = 0; nt < 16; ++nt) {
        int key = 128 * g + 8 * nt + c0;
        bool v0 = idx_s[key] >= 0, v1 = idx_s[key + 1] >= 0;
        acc[nt][0] *= SCALE_F; acc[nt][1] *= SCALE_F;
        acc[nt][2] *= SCALE_F; acc[nt][3] *= SCALE_F;
        if (v0) { m0 = fmaxf(m0, acc[nt][0]); m1 = fmaxf(m1, acc[nt][2]); vm |= 1u << (2*nt); }
        if (v1) { m0 = fmaxf(m0, acc[nt][1]); m1 = fmaxf(m1, acc[nt][3]); vm |= 2u << (2*nt); }
    }
    m0 = fmaxf(m0, __shfl_xor_sync(0xffffffffu, m0, 1));
    m0 = fmaxf(m0, __shfl_xor_sync(0xffffffffu, m0, 2));
    m1 = fmaxf(m1, __shfl_xor_sync(0xffffffffu, m1, 1));
    m1 = fmaxf(m1, __shfl_xor_sync(0xffffffffu, m1, 2));
    if ((lane & 3) == 0) { redm[h0 * 4 + g] = m0; redm[h1 * 4 + g] = m1; }
    __syncthreads();
    float sk0 = sink[h0], sk1 = sink[h1];
    float mf0 = fmaxf(fmaxf(fmaxf(redm[h0*4+0], redm[h0*4+1]), fmaxf(redm[h0*4+2], redm[h0*4+3])), sk0);
    float mf1 = fmaxf(fmaxf(fmaxf(redm[h1*4+0], redm[h1*4+1]), fmaxf(redm[h1*4+2], redm[h1*4+3])), sk1);
    float l0 = 0.f, l1 = 0.f;
    #pragma unroll
    for (int nt = 0; nt < 16; ++nt) {
        int key = 128 * g + 8 * nt + c0;
        float p00 = ((vm >> (2*nt)) & 1) ? __expf(acc[nt][0] - mf0) : 0.f;
        float p01 = ((vm >> (2*nt)) & 2) ? __expf(acc[nt][1] - mf0) : 0.f;
        float p10 = ((vm >> (2*nt)) & 1) ? __expf(acc[nt][2] - mf1) : 0.f;
        float p11 = ((vm >> (2*nt)) & 2) ? __expf(acc[nt][3] - mf1) : 0.f;
        l0 += p00 + p01; l1 += p10 + p11;
        __nv_bfloat16 a0 = __float2bfloat16_rn(p00), a1 = __float2bfloat16_rn(p01);
        __nv_bfloat16 b0 = __float2bfloat16_rn(p10), b1 = __float2bfloat16_rn(p11);
        *(__nv_bfloat162*)(smem + P_HI + h0 * 1040 + key * 2) = __nv_bfloat162(a0, a1);
        *(__nv_bfloat162*)(smem + P_HI + h1 * 1040 + key * 2) = __nv_bfloat162(b0, b1);
        *(__nv_bfloat162*)(smem + P_LO + h0 * 1040 + key * 2) =
            __nv_bfloat162(__float2bfloat16_rn(p00 - __bfloat162float(a0)),
                           __float2bfloat16_rn(p01 - __bfloat162float(a1)));
        *(__nv_bfloat162*)(smem + P_LO + h1 * 1040 + key * 2) =
            __nv_bfloat162(__float2bfloat16_rn(p10 - __bfloat162float(b0)),
                           __float2bfloat16_rn(p11 - __bfloat162float(b1)));
    }
    l0 += __shfl_xor_sync(0xffffffffu, l0, 1);
    l0 += __shfl_xor_sync(0xffffffffu, l0, 2);
    l1 += __shfl_xor_sync(0xffffffffu, l1, 1);
    l1 += __shfl_xor_sync(0xffffffffu, l1, 2);
    if ((lane & 3) == 0) { reds[h0 * 4 + g] = l0; reds[h1 * 4 + g] = l1; }
    __syncthreads();
    if (g == 0 && (lane & 3) == 0) {
        float la = reds[h0*4+0] + reds[h0*4+1] + reds[h0*4+2] + reds[h0*4+3] + __expf(sk0 - mf0);
        float lb = reds[h1*4+0] + reds[h1*4+1] + reds[h1*4+2] + reds[h1*4+3] + __expf(sk1 - mf1);
        lh[h0] = 1.0f / la;
        lh[h1] = 1.0f / lb;
    }

    // zero accumulators for GEMM2
    #pragma unroll
    for (int i = 0; i < 16; ++i)
        #pragma unroll
        for (int j = 0; j < 4; ++j) acc[i][j] = 0.f;

    // ================= GEMM2: O = P V, 32 key tiles of 16, pipelined =================
    int vbuf = 0;
    #pragma unroll 1
    for (int vt = 0; vt < 32; ++vt) {
        int nb = vbuf ^ 1;
        if (vt + 1 < 32) { issueV(vt + 1, nb); CP_COMMIT(); CP_WAIT1(); }
        else             { CP_WAIT0(); }
        __syncthreads();
        {
            uint32_t ap = sbase + P_HI + (16 * hb + lo16) * 1040 + hi16 * 16 + vt * 32;
            uint32_t vb = sbase + VB0 + vbuf * 33280 + lo16 * 1040 + hi16 * 16 + 256 * g;
            uint32_t aH[4], aL[4];
            ldsm_x4(aH, ap);
            ldsm_x4(aL, ap + 66560);
            #pragma unroll
            for (int np = 0; np < 8; ++np) {
                uint32_t bH[4], bL[4];
                ldsm_x4t(bH, vb + np * 32);
                ldsm_x4t(bL, vb + 16640 + np * 32);
                mma_bf16(acc[2*np],   aH, bH[0], bH[1]);
                mma_bf16(acc[2*np],   aH, bL[0], bL[1]);
                mma_bf16(acc[2*np],   aL, bH[0], bH[1]);
                mma_bf16(acc[2*np+1], aH, bH[2], bH[3]);
                mma_bf16(acc[2*np+1], aH, bL[2], bL[3]);
                mma_bf16(acc[2*np+1], aL, bH[2], bH[3]);
            }
        }
        __syncthreads();
        vbuf = nb;
    }

    // ================= normalize + write =================
    float li0 = lh[h0], li1 = lh[h1];
    float* ob0 = outg + ((size_t)t * NHD + h0) * DV + 128 * g + c0;
    float* ob1 = outg + ((size_t)t * NHD + h1) * DV + 128 * g + c0;
    #pragma unroll
    for (int nt = 0; nt < 16; ++nt) {
        float2 v0 = make_float2(acc[nt][0] * li0, acc[nt][1] * li0);
        float2 v1 = make_float2(acc[nt][2] * li1, acc[nt][3] * li1);
        *(float2*)(ob0 + 8 * nt) = v0;
        *(float2*)(ob1 + 8 * nt) = v1;
    }
}

// ---------------- launcher ----------------
extern "C" void kernel_launch(void* const* d_in, const int* in_sizes, int n_in,
                              void* d_out, int out_size)
{
    const float* q    = (const float*)d_in[0];
    const float* kv   = (const float*)d_in[1];
    const int*   topk = (const int*)d_in[2];
    const float* sink = (const float*)d_in[3];
    float* out = (float*)d_out;

    const int n4 = 4718592;   // 32768*576/4
    conv_kv_kernel<<<n4 / 256, 256>>>((const float4*)kv);

    cudaFuncSetAttribute(mla_mma_kernel,
                         cudaFuncAttributeMaxDynamicSharedMemorySize, SMEM_TOTAL);
    mla_mma_kernel<<<TTOK, NTHR, SMEM_TOTAL>>>(q, topk, sink, out);
}